// round 16
// baseline (speedup 1.0000x reference)
#include <cuda_runtime.h>
#include <cuda_bf16.h>
#include <cstdint>

#define BATCH 4096
#define BB    8192      // both branches concatenated
#define FDIM  58
#define TT    30
#define H1    512
#define H2    128
#define H3    64

// two-limb int8 scheme, radix 254: v ~= scale * (254*hi + lo) / 32258
// hi = round(127 v); lo = round(254*(127 v - hi)) uses the FULL int8 range.
#define QF    127.0f
#define RF    254.0f
#define Q2F   32258.0f
#define R2F   64516.0f
#define INVQ4 9.610016e-10f   // 1 / 32258^2

// ---------------- static device scratch ----------------
__device__ int8_t g_Xq [(size_t)BB*TT*64],  g_Xr [(size_t)BB*TT*64];
__device__ int8_t g_S1q[(size_t)BB*TT*H1],  g_S1r[(size_t)BB*TT*H1];
__device__ int8_t g_S2q[(size_t)BB*TT*H2],  g_S2r[(size_t)BB*TT*H2];
__device__ float  g_H3seq[(size_t)BB*TT*H3];
__device__ int8_t g_HAq[(size_t)BB*H1], g_HAr[(size_t)BB*H1];
__device__ int8_t g_HBq[(size_t)BB*H1], g_HBr[(size_t)BB*H1];
__device__ float  g_C  [(size_t)BB*H1];
__device__ int8_t g_W1q[2048*576], g_W1r[2048*576];   // [n=h*4+g][k]
__device__ int8_t g_W2q[512*640],  g_W2r[512*640];
__device__ int8_t g_W3q[256*192],  g_W3r[256*192];
__device__ float  g_sc1[2048], g_sc2[512], g_sc3[256]; // sigma_n * INVQ4
__device__ float  g_b1p[2048], g_b2p[512], g_b3p[256];
__device__ unsigned g_sxBits;                          // max |x| as uint bits
__device__ float g_Wf1p[1920*960], g_Wf2p[960*480];
__device__ float g_D [(size_t)BATCH*1920];
__device__ float g_F1[(size_t)BATCH*960];
__device__ float g_F2[(size_t)BATCH*480];

// ---------------- helpers ----------------
__device__ __forceinline__ uint32_t smem_u32(const void* p) {
    uint32_t a;
    asm("{ .reg .u64 t; cvta.to.shared.u64 t, %1; cvt.u32.u64 %0, t; }" : "=r"(a) : "l"(p));
    return a;
}
__device__ __forceinline__ float tanha(float x) {
    float y;
    asm("tanh.approx.f32 %0, %1;" : "=f"(y) : "f"(x));
    return y;
}
__device__ __forceinline__ float sigm(float x) { return fmaf(tanha(x*0.5f), 0.5f, 0.5f); }

// quantize a in [-1,1] to two int8 limbs: 254*hi + lo ~= a*32258
__device__ __forceinline__ void q15(float a, int8_t& hi, int8_t& lo) {
    int h = __float2int_rn(a * QF);
    int l = __float2int_rn(fmaf(-RF, (float)h, a * Q2F));
    hi = (int8_t)h; lo = (int8_t)l;
}

#define CP_ASYNC16(sm, gp) \
    asm volatile("cp.async.cg.shared.global [%0], [%1], 16;" :: "r"(sm), "l"(gp) : "memory")
#define CP_COMMIT() asm volatile("cp.async.commit_group;" ::: "memory")
#define CP_WAIT0()  asm volatile("cp.async.wait_group 0;" ::: "memory")
#define CP_WAIT1()  asm volatile("cp.async.wait_group 1;" ::: "memory")

#define MMA_S8(c, a, b) \
    asm volatile("mma.sync.aligned.m16n8k32.row.col.s32.s8.s8.s32 " \
        "{%0,%1,%2,%3}, {%4,%5,%6,%7}, {%8,%9}, {%0,%1,%2,%3};" \
        : "+r"((c)[0]), "+r"((c)[1]), "+r"((c)[2]), "+r"((c)[3]) \
        : "r"((a)[0]), "r"((a)[1]), "r"((a)[2]), "r"((a)[3]), "r"((b)[0]), "r"((b)[1]))

// ---------------- packing ----------------
// pass 1: global max |x| (deterministic across replays: max of same data)
__global__ void pack_x_max(const float* __restrict__ x1, const float* __restrict__ x2)
{
    const int N = BATCH*FDIM*TT;
    for (int i = blockIdx.x*blockDim.x + threadIdx.x; i < 2*N; i += gridDim.x*blockDim.x) {
        float v = fabsf(i < N ? x1[i] : x2[i - N]);
        atomicMax(&g_sxBits, __float_as_uint(v));
    }
}

// pass 2: x' = x / sX quantized to two limbs, layout [bb][t][64] (58 padded)
__global__ void pack_x_quant(const float* __restrict__ x1, const float* __restrict__ x2)
{
    int idx = blockIdx.x*blockDim.x + threadIdx.x;
    if (idx >= BB*TT*64) return;
    float sX = fmaxf(__uint_as_float(g_sxBits), 1e-20f);
    int k   = idx & 63;
    int tmp = idx >> 6;
    int t   = tmp % TT;
    int bb  = tmp / TT;
    const float* src = (bb < BATCH) ? x1 : x2;
    int bs = (bb < BATCH) ? bb : bb - BATCH;
    float v = (k < FDIM) ? src[((size_t)bs*FDIM + k)*TT + t] : 0.f;
    int8_t hi, lo;
    q15(v / sX, hi, lo);
    g_Xq[idx] = hi; g_Xr[idx] = lo;
}

// pack weights (per-column sigma + two-limb quantize; sX folded into Wih of layer 1),
// biases, and zero the h/c state. All destinations resolved inside device code.
__global__ void pack_all(const float* __restrict__ Wih1, const float* __restrict__ Whh1,
                         const float* __restrict__ b1,
                         const float* __restrict__ Wih2, const float* __restrict__ Whh2,
                         const float* __restrict__ b2,
                         const float* __restrict__ Wih3, const float* __restrict__ Whh3,
                         const float* __restrict__ b3)
{
    int i = blockIdx.x*blockDim.x + threadIdx.x;
    if (i < BB*H1) { g_HAq[i] = 0; g_HAr[i] = 0; g_C[i] = 0.f; }

    if (i < 2816) {
        // bias pack (gate-interleaved)
        if (i < 2048)      { int h = i >> 2, g = i & 3; g_b1p[i] = b1[g*H1 + h]; }
        else if (i < 2560) { int c = i - 2048, h = c >> 2, g = c & 3; g_b2p[c] = b2[g*H2 + h]; }
        else               { int c = i - 2560, h = c >> 2, g = c & 3; g_b3p[c] = b3[g*H3 + h]; }

        // weight column pack
        int L, n, H, INR, KT;
        const float *Wih, *Whh;
        int8_t *Wq, *Wr; float *sc;
        if (i < 2048)      { L=1; n=i;      H=H1; INR=FDIM; KT=576; Wih=Wih1; Whh=Whh1; Wq=g_W1q; Wr=g_W1r; sc=g_sc1; }
        else if (i < 2560) { L=2; n=i-2048; H=H2; INR=H1;   KT=640; Wih=Wih2; Whh=Whh2; Wq=g_W2q; Wr=g_W2r; sc=g_sc2; }
        else               { L=3; n=i-2560; H=H3; INR=H2;   KT=192; Wih=Wih3; Whh=Whh3; Wq=g_W3q; Wr=g_W3r; sc=g_sc3; }
        float sX = fmaxf(__uint_as_float(g_sxBits), 1e-20f);
        int h = n >> 2, g = n & 3;
        float sig = 1e-20f;
        for (int k = 0; k < KT; k++) {
            float v;
            if (k < H) v = Whh[(size_t)(g*H + h)*H + k];
            else {
                int kk = k - H;
                v = (kk < INR) ? Wih[(size_t)(g*H + h)*INR + kk] : 0.f;
                if (L == 1) v *= sX;
            }
            sig = fmaxf(sig, fabsf(v));
        }
        sc[n] = sig * INVQ4;
        float inv = 1.0f / sig;
        for (int k = 0; k < KT; k++) {
            float v;
            if (k < H) v = Whh[(size_t)(g*H + h)*H + k];
            else {
                int kk = k - H;
                v = (kk < INR) ? Wih[(size_t)(g*H + h)*INR + kk] : 0.f;
                if (L == 1) v *= sX;
            }
            int8_t hi, lo;
            q15(v * inv, hi, lo);
            Wq[(size_t)n*KT + k] = hi;
            Wr[(size_t)n*KT + k] = lo;
        }
    }
}

__global__ void zero_h()
{
    int i = blockIdx.x*blockDim.x + threadIdx.x;
    if (i < BB*H1) { g_HAq[i] = 0; g_HAr[i] = 0; g_C[i] = 0.f; }
}

// ---------------- fused IMMA LSTM step (exact 4-product two-limb, radix 254) ----------------
// D[64x64] = [Hprev ; x_t] x W^T via int8 two-limb, EXACT: 64516*hh + 254*(hl+lh) + ll
// (4 IMMA per k32). Then LSTM cell. 256 threads = 8 warps (2 M x 4 N), warp tile 32x16.
// smem: 2-stage, kquad words [row][12] (stride 12 = conflict-free), 24 KB static.
template<int H, int IN, int LAYER>
__global__ __launch_bounds__(256, 2) void lstm_step(int t)
{
    constexpr int KT  = H + IN;
    constexpr int NCH = KT / 32;

    __shared__ __align__(16) uint32_t sAq[2][64][12];
    __shared__ __align__(16) uint32_t sAr[2][64][12];
    __shared__ __align__(16) uint32_t sBq[2][64][12];
    __shared__ __align__(16) uint32_t sBr[2][64][12];

    const int tid  = threadIdx.x;
    const int wid  = tid >> 5;
    const int lane = tid & 31;
    const int m0   = blockIdx.x * 64;
    const int n0   = blockIdx.y * 64;
    const int wm   = (wid >> 2) * 32;   // 2 warps in M
    const int wn   = (wid & 3) * 16;    // 4 warps in N
    const int g    = lane >> 2;         // 0..7
    const int tig  = lane & 3;          // 0..3

    const int8_t *Hpq, *Hpr, *Xq, *Xr, *Wq, *Wr;
    const float *bp, *scp;
    int8_t *Hnq, *Hnr, *Sq = nullptr, *Sr = nullptr;
    if constexpr (LAYER == 1) { Xq = g_Xq;  Xr = g_Xr;  Wq = g_W1q; Wr = g_W1r; bp = g_b1p; scp = g_sc1; Sq = g_S1q; Sr = g_S1r; }
    else if constexpr (LAYER == 2) { Xq = g_S1q; Xr = g_S1r; Wq = g_W2q; Wr = g_W2r; bp = g_b2p; scp = g_sc2; Sq = g_S2q; Sr = g_S2r; }
    else { Xq = g_S2q; Xr = g_S2r; Wq = g_W3q; Wr = g_W3r; bp = g_b3p; scp = g_sc3; }
    Hpq = (t & 1) ? g_HBq : g_HAq;
    Hpr = (t & 1) ? g_HBr : g_HAr;
    Hnq = (t & 1) ? g_HAq : g_HBq;
    Hnr = (t & 1) ? g_HAr : g_HBr;

    int32_t acc1[2][2][4], acc2[2][2][4], acc3[2][2][4];
    #pragma unroll
    for (int i = 0; i < 2; i++)
        #pragma unroll
        for (int j = 0; j < 2; j++)
            #pragma unroll
            for (int k = 0; k < 4; k++) { acc1[i][j][k] = 0; acc2[i][j][k] = 0; acc3[i][j][k] = 0; }

    // fill coordinates: tid<128 -> A (both limbs), tid>=128 -> B (both limbs)
    const int fu = tid & 127;
    const int fr = fu >> 1;          // row 0..63
    const int fq = (fu & 1) * 4;     // word offset (0 or 4) == 16B quarter

    auto fill = [&](int ch, int stg) {
        const int k0 = ch * 32;
        const bool st = (k0 < H);
        if (tid < 128) {
            const int8_t *aq, *ar;
            if (st) { aq = Hpq + (size_t)(m0 + fr)*H + k0;
                      ar = Hpr + (size_t)(m0 + fr)*H + k0; }
            else    { aq = Xq + ((size_t)(m0 + fr)*TT + t)*IN + (k0 - H);
                      ar = Xr + ((size_t)(m0 + fr)*TT + t)*IN + (k0 - H); }
            CP_ASYNC16(smem_u32(&sAq[stg][fr][fq]), aq + fq*4);
            CP_ASYNC16(smem_u32(&sAr[stg][fr][fq]), ar + fq*4);
        } else {
            CP_ASYNC16(smem_u32(&sBq[stg][fr][fq]), Wq + (size_t)(n0 + fr)*KT + k0 + fq*4);
            CP_ASYNC16(smem_u32(&sBr[stg][fr][fq]), Wr + (size_t)(n0 + fr)*KT + k0 + fq*4);
        }
        CP_COMMIT();
    };

    fill(0, 0);

    for (int ch = 0; ch < NCH; ch++) {
        const int stg = ch & 1;
        const bool more = (ch + 1 < NCH);
        if (more) fill(ch + 1, stg ^ 1);
        if (more) { CP_WAIT1(); } else { CP_WAIT0(); }
        __syncthreads();

        const uint32_t (*cAq)[12] = sAq[stg];
        const uint32_t (*cAr)[12] = sAr[stg];
        const uint32_t (*cBq)[12] = sBq[stg];
        const uint32_t (*cBr)[12] = sBr[stg];

        uint32_t bq[2][2], br[2][2];
        #pragma unroll
        for (int j = 0; j < 2; j++) {
            int col = wn + j*8 + g;
            bq[j][0] = cBq[col][tig];  bq[j][1] = cBq[col][tig + 4];
            br[j][0] = cBr[col][tig];  br[j][1] = cBr[col][tig + 4];
        }
        #pragma unroll
        for (int i = 0; i < 2; i++) {
            int row = wm + i*16 + g;
            uint32_t aq[4], ar[4];
            aq[0] = cAq[row    ][tig];     aq[1] = cAq[row + 8][tig];
            aq[2] = cAq[row    ][tig + 4]; aq[3] = cAq[row + 8][tig + 4];
            ar[0] = cAr[row    ][tig];     ar[1] = cAr[row + 8][tig];
            ar[2] = cAr[row    ][tig + 4]; ar[3] = cAr[row + 8][tig + 4];
            #pragma unroll
            for (int j = 0; j < 2; j++) {
                MMA_S8(acc1[i][j], aq, bq[j]);   // hi*hi
                MMA_S8(acc2[i][j], aq, br[j]);   // hi*lo
                MMA_S8(acc2[i][j], ar, bq[j]);   // lo*hi
                MMA_S8(acc3[i][j], ar, br[j]);   // lo*lo (exactness term)
            }
        }
        __syncthreads();
    }

    // ---- epilogue: exact limb combine, shuffle-assemble gate quadruples, LSTM cell ----
    #pragma unroll
    for (int i = 0; i < 2; i++) {
        #pragma unroll
        for (int j = 0; j < 2; j++) {
            float c0 = fmaf(R2F, (float)acc1[i][j][0], fmaf(RF, (float)acc2[i][j][0], (float)acc3[i][j][0]));
            float c1 = fmaf(R2F, (float)acc1[i][j][1], fmaf(RF, (float)acc2[i][j][1], (float)acc3[i][j][1]));
            float c2 = fmaf(R2F, (float)acc1[i][j][2], fmaf(RF, (float)acc2[i][j][2], (float)acc3[i][j][2]));
            float c3 = fmaf(R2F, (float)acc1[i][j][3], fmaf(RF, (float)acc2[i][j][3], (float)acc3[i][j][3]));
            float s0 = __shfl_xor_sync(0xffffffffu, c0, 1);
            float s1 = __shfl_xor_sync(0xffffffffu, c1, 1);
            float s2 = __shfl_xor_sync(0xffffffffu, c2, 1);
            float s3 = __shfl_xor_sync(0xffffffffu, c3, 1);
            int row, nb;
            float g0, g1, g2, g3;
            if (!(lane & 1)) { row = wm + i*16 + g;     nb = wn + j*8 + tig*2;     g0 = c0; g1 = c1; g2 = s0; g3 = s1; }
            else             { row = wm + i*16 + g + 8; nb = wn + j*8 + tig*2 - 2; g0 = s2; g1 = s3; g2 = c2; g3 = c3; }

            const size_t m = (size_t)(m0 + row);
            const int n  = n0 + nb;            // gate-i column (n % 4 == 0)
            const int jh = n >> 2;             // h column
            float gi = fmaf(scp[n + 0], g0, bp[n + 0]);
            float gf = fmaf(scp[n + 1], g1, bp[n + 1]);
            float gg = fmaf(scp[n + 2], g2, bp[n + 2]);
            float go = fmaf(scp[n + 3], g3, bp[n + 3]);
            float iv = sigm(gi);
            float fv = sigm(gf);
            float gv = tanha(gg);
            float ov = sigm(go);
            float c  = fv * g_C[m*H + jh] + iv * gv;
            g_C[m*H + jh] = c;
            float h  = ov * tanha(c);
            int8_t hq, hr;
            q15(h, hq, hr);
            Hnq[m*H + jh] = hq;
            Hnr[m*H + jh] = hr;
            float rh = fmaxf(h, 0.f);
            if constexpr (LAYER == 3) {
                g_H3seq[(m*TT + t)*H3 + jh] = rh;
            } else {
                int8_t rq, rr;
                q15(rh, rq, rr);
                Sq[(m*TT + t)*H + jh] = rq;
                Sr[(m*TT + t)*H + jh] = rr;
            }
        }
    }
}

// ---------------- FC weight packs ----------------
__global__ void pack_wf1(const float* __restrict__ Wf1)
{
    int idx = blockIdx.x*blockDim.x + threadIdx.x;
    if (idx >= 1920*960) return;
    int k = idx / 960, n = idx % 960;
    g_Wf1p[idx] = Wf1[(size_t)n*1920 + k];
}
__global__ void pack_wf2(const float* __restrict__ Wf2)
{
    int idx = blockIdx.x*blockDim.x + threadIdx.x;
    if (idx >= 960*480) return;
    int k = idx / 480, n = idx % 480;
    g_Wf2p[idx] = Wf2[(size_t)n*960 + k];
}

// ---------------- guarded SGEMM + bias + relu for FC layers (proven) ----------------
template<int ID>
__global__ __launch_bounds__(256) void fc_gemm(const float* __restrict__ bias,
                                               int M, int N, int K)
{
    const float* __restrict__ A;
    const float* __restrict__ Bw;
    float*       __restrict__ Co;
    if constexpr (ID == 1) { A = g_D;  Bw = g_Wf1p; Co = g_F1; }
    else                   { A = g_F1; Bw = g_Wf2p; Co = g_F2; }

    __shared__ float As[16][132];
    __shared__ float Bs[16][128];

    const int m0  = blockIdx.x * 128;
    const int n0  = blockIdx.y * 128;
    const int tid = threadIdx.x;
    const int tx  = tid & 15;
    const int ty  = tid >> 4;

    float acc[8][8];
    #pragma unroll
    for (int i = 0; i < 8; i++)
        #pragma unroll
        for (int j = 0; j < 8; j++) acc[i][j] = 0.f;

    const int kl = tid & 15;
    const int ml = tid >> 4;
    const int bn = tid & 127;
    const int bk = (tid >> 7) * 8;

    for (int k0 = 0; k0 < K; k0 += 16) {
        const int kA = k0 + kl;
        #pragma unroll
        for (int i = 0; i < 8; i++) {
            int m = m0 + ml + 16*i;
            As[kl][ml + 16*i] = (kA < K) ? A[(size_t)m*K + kA] : 0.f;
        }
        const int n = n0 + bn;
        #pragma unroll
        for (int i = 0; i < 8; i++) {
            int k = k0 + bk + i;
            Bs[bk + i][bn] = (k < K && n < N) ? Bw[(size_t)k*N + n] : 0.f;
        }
        __syncthreads();
        #pragma unroll
        for (int kk = 0; kk < 16; kk++) {
            float a[8], b[8];
            #pragma unroll
            for (int i = 0; i < 8; i++) a[i] = As[kk][ty*8 + i];
            #pragma unroll
            for (int j = 0; j < 8; j++) b[j] = Bs[kk][tx*8 + j];
            #pragma unroll
            for (int i = 0; i < 8; i++)
                #pragma unroll
                for (int j = 0; j < 8; j++) acc[i][j] += a[i]*b[j];
        }
        __syncthreads();
    }

    #pragma unroll
    for (int i = 0; i < 8; i++) {
        const int m = m0 + ty*8 + i;
        #pragma unroll
        for (int j = 0; j < 8; j++) {
            const int n = n0 + tx*8 + j;
            if (n < N)
                Co[(size_t)m*N + n] = fmaxf(acc[i][j] + bias[n], 0.f);
        }
    }
}

// ---------------- |h1 - h2| ----------------
__global__ void diff_kernel()
{
    int idx = blockIdx.x*blockDim.x + threadIdx.x;
    if (idx >= BATCH*1920) return;
    int b = idx / 1920;
    int r = idx % 1920;
    int t = r / 64, h = r % 64;
    float a = g_H3seq[((size_t)b*TT + t)*64 + h];
    float c = g_H3seq[((size_t)(b + BATCH)*TT + t)*64 + h];
    g_D[idx] = fabsf(a - c);
}

// ---------------- fused FC3 + FC4 head ----------------
__global__ __launch_bounds__(256) void head_kernel(const float* __restrict__ Wf3,
                                                   const float* __restrict__ bf3,
                                                   const float* __restrict__ Wf4,
                                                   const float* __restrict__ bf4,
                                                   float* __restrict__ out)
{
    __shared__ float w3[16*480];
    __shared__ float w4[16];
    __shared__ float b3s[16];
    for (int i = threadIdx.x; i < 16*480; i += blockDim.x) w3[i] = Wf3[i];
    if (threadIdx.x < 16) { w4[threadIdx.x] = Wf4[threadIdx.x]; b3s[threadIdx.x] = bf3[threadIdx.x]; }
    __syncthreads();

    int b = blockIdx.x*blockDim.x + threadIdx.x;
    if (b >= BATCH) return;

    float acc[16];
    #pragma unroll
    for (int j = 0; j < 16; j++) acc[j] = b3s[j];

    const float* __restrict__ row = g_F2 + (size_t)b*480;
    for (int k = 0; k < 480; k++) {
        float v = row[k];
        #pragma unroll
        for (int j = 0; j < 16; j++) acc[j] += v * w3[j*480 + k];
    }
    float o = bf4[0];
    #pragma unroll
    for (int j = 0; j < 16; j++) o += fmaxf(acc[j], 0.f) * w4[j];
    out[b] = o;
}

// ---------------- launch ----------------
extern "C" void kernel_launch(void* const* d_in, const int* in_sizes, int n_in,
                              void* d_out, int out_size)
{
    const float* x1   = (const float*)d_in[0];
    const float* x2   = (const float*)d_in[1];
    const float* Wih1 = (const float*)d_in[2];
    const float* Whh1 = (const float*)d_in[3];
    const float* b1   = (const float*)d_in[4];
    const float* Wih2 = (const float*)d_in[5];
    const float* Whh2 = (const float*)d_in[6];
    const float* b2   = (const float*)d_in[7];
    const float* Wih3 = (const float*)d_in[8];
    const float* Whh3 = (const float*)d_in[9];
    const float* b3   = (const float*)d_in[10];
    const float* Wf1  = (const float*)d_in[11];
    const float* bf1  = (const float*)d_in[12];
    const float* Wf2  = (const float*)d_in[13];
    const float* bf2  = (const float*)d_in[14];
    const float* Wf3  = (const float*)d_in[15];
    const float* bf3  = (const float*)d_in[16];
    const float* Wf4  = (const float*)d_in[17];
    const float* bf4  = (const float*)d_in[18];
    float* out = (float*)d_out;

    pack_x_max  <<<512, 256>>>(x1, x2);
    pack_x_quant<<<(BB*TT*64 + 255)/256, 256>>>(x1, x2);
    pack_all    <<<(BB*H1 + 255)/256, 256>>>(Wih1, Whh1, b1, Wih2, Whh2, b2, Wih3, Whh3, b3);

    // layer 1: 58 -> 512   (KT = 576)
    for (int t = 0; t < TT; t++)
        lstm_step<H1, 64, 1><<<dim3(BB/64, (4*H1)/64), 256>>>(t);

    // layer 2: 512 -> 128  (KT = 640)
    zero_h<<<(BB*H1 + 255)/256, 256>>>();
    for (int t = 0; t < TT; t++)
        lstm_step<H2, H1, 2><<<dim3(BB/64, (4*H2)/64), 256>>>(t);

    // layer 3: 128 -> 64   (KT = 192)
    zero_h<<<(BB*H1 + 255)/256, 256>>>();
    for (int t = 0; t < TT; t++)
        lstm_step<H3, H2, 3><<<dim3(BB/64, (4*H3)/64), 256>>>(t);

    pack_wf1<<<(1920*960 + 255)/256, 256>>>(Wf1);
    pack_wf2<<<(960*480  + 255)/256, 256>>>(Wf2);

    diff_kernel<<<(BATCH*1920 + 255)/256, 256>>>();

    fc_gemm<1><<<dim3(BATCH/128, (960 + 127)/128), 256>>>(bf1, BATCH, 960, 1920);
    fc_gemm<2><<<dim3(BATCH/128, (480 + 127)/128), 256>>>(bf2, BATCH, 480, 960);
    head_kernel<<<(BATCH + 255)/256, 256>>>(Wf3, bf3, Wf4, bf4, out);
}

// round 17
// speedup vs baseline: 1.9914x; 1.9914x over previous
#include <cuda_runtime.h>
#include <cuda_fp16.h>
#include <cstdint>

#define BATCH 4096
#define BB    8192      // both branches concatenated
#define FDIM  58
#define TT    30
#define H1    512
#define H2    128
#define H3    64

// ---------------- static device scratch (fp16 hi/lo planar) ----------------
__device__ __half g_Xh [(size_t)BB*TT*64],  g_Xl [(size_t)BB*TT*64];
__device__ __half g_S1h[(size_t)BB*TT*H1],  g_S1l[(size_t)BB*TT*H1];
__device__ __half g_S2h[(size_t)BB*TT*H2],  g_S2l[(size_t)BB*TT*H2];
__device__ float  g_H3seq[(size_t)BB*TT*H3];
__device__ __half g_HAh[(size_t)BB*H1], g_HAl[(size_t)BB*H1];
__device__ __half g_HBh[(size_t)BB*H1], g_HBl[(size_t)BB*H1];
__device__ float  g_C  [(size_t)BB*H1];
__device__ __half g_W1h[2048*576], g_W1l[2048*576];   // [n=h*4+g][k]
__device__ __half g_W2h[512*640],  g_W2l[512*640];
__device__ __half g_W3h[256*192],  g_W3l[256*192];
__device__ float  g_b1p[2048], g_b2p[512], g_b3p[256];
__device__ float  g_Wf1p[1920*960], g_Wf2p[960*480];
__device__ float  g_D [(size_t)BATCH*1920];
__device__ float  g_F1[(size_t)BATCH*960];
__device__ float  g_F2[(size_t)BATCH*480];

// ---------------- helpers ----------------
__device__ __forceinline__ uint32_t smem_u32(const void* p) {
    uint32_t a;
    asm("{ .reg .u64 t; cvta.to.shared.u64 t, %1; cvt.u32.u64 %0, t; }" : "=r"(a) : "l"(p));
    return a;
}
__device__ __forceinline__ float tanha(float x) {
    float y;
    asm("tanh.approx.f32 %0, %1;" : "=f"(y) : "f"(x));
    return y;
}
__device__ __forceinline__ float sigm(float x) { return fmaf(tanha(x*0.5f), 0.5f, 0.5f); }

__device__ __forceinline__ void h2split(float v, __half& hi, __half& lo) {
    hi = __float2half_rn(v);
    lo = __float2half_rn(v - __half2float(hi));
}

#define CP_ASYNC16(sm, gp) \
    asm volatile("cp.async.cg.shared.global [%0], [%1], 16;" :: "r"(sm), "l"(gp) : "memory")
#define CP_COMMIT() asm volatile("cp.async.commit_group;" ::: "memory")
#define CP_WAIT0()  asm volatile("cp.async.wait_group 0;" ::: "memory")

#define MMA_F16_ACC32(c, a, b) \
    asm volatile("mma.sync.aligned.m16n8k16.row.col.f32.f16.f16.f32 " \
        "{%0,%1,%2,%3}, {%4,%5,%6,%7}, {%8,%9}, {%0,%1,%2,%3};" \
        : "+f"((c)[0]), "+f"((c)[1]), "+f"((c)[2]), "+f"((c)[3]) \
        : "r"((a)[0]), "r"((a)[1]), "r"((a)[2]), "r"((a)[3]), "r"((b)[0]), "r"((b)[1]))

#define MMA_F16_ACC16(c, a, b) \
    asm volatile("mma.sync.aligned.m16n8k16.row.col.f16.f16.f16.f16 " \
        "{%0,%1}, {%2,%3,%4,%5}, {%6,%7}, {%0,%1};" \
        : "+r"((c)[0]), "+r"((c)[1]) \
        : "r"((a)[0]), "r"((a)[1]), "r"((a)[2]), "r"((a)[3]), "r"((b)[0]), "r"((b)[1]))

// ---------------- packing ----------------
__global__ void pack_x_hilo(const float* __restrict__ x1, const float* __restrict__ x2)
{
    int idx = blockIdx.x*blockDim.x + threadIdx.x;
    if (idx >= BB*TT*64) return;
    int k   = idx & 63;
    int tmp = idx >> 6;
    int t   = tmp % TT;
    int bb  = tmp / TT;
    const float* src = (bb < BATCH) ? x1 : x2;
    int bs = (bb < BATCH) ? bb : bb - BATCH;
    float v = (k < FDIM) ? src[((size_t)bs*FDIM + k)*TT + t] : 0.f;
    __half hi, lo;
    h2split(v, hi, lo);
    g_Xh[idx] = hi;
    g_Xl[idx] = lo;
}

// weights: [n = h*4+gate][k], k<H: Whh, k>=H: Wih (zero-padded), fp16 hi/lo.
// Destinations selected INSIDE device code (never pass __device__ globals as
// kernel args from host — that passes the host shadow symbol!).
template<int LAYER>
__global__ void pack_wb(const float* __restrict__ Wih, const float* __restrict__ Whh)
{
    constexpr int H   = (LAYER == 1) ? H1 : (LAYER == 2) ? H2 : H3;
    constexpr int INR = (LAYER == 1) ? FDIM : (LAYER == 2) ? H1 : H2;
    constexpr int IN  = (LAYER == 1) ? 64 : (LAYER == 2) ? H1 : H2;
    constexpr int KT  = H + IN;
    __half* Wh;
    __half* Wl;
    if constexpr (LAYER == 1)      { Wh = g_W1h; Wl = g_W1l; }
    else if constexpr (LAYER == 2) { Wh = g_W2h; Wl = g_W2l; }
    else                           { Wh = g_W3h; Wl = g_W3l; }

    int idx = blockIdx.x*blockDim.x + threadIdx.x;
    if (idx >= 4*H*KT) return;
    int n = idx / KT, k = idx % KT;
    int h = n >> 2, g = n & 3;
    float v;
    if (k < H) v = Whh[(size_t)(g*H + h)*H + k];
    else {
        int kk = k - H;
        v = (kk < INR) ? Wih[(size_t)(g*H + h)*INR + kk] : 0.f;
    }
    __half hi, lo;
    h2split(v, hi, lo);
    Wh[idx] = hi;
    Wl[idx] = lo;
}

// zero h/c state; first call also packs the gate-interleaved biases
template<bool WITH_BIAS>
__global__ void zero_state_bias(const float* b1, const float* b2, const float* b3)
{
    int i = blockIdx.x*blockDim.x + threadIdx.x;
    if (i < BB*H1) {
        g_HAh[i] = __float2half(0.f);
        g_HAl[i] = __float2half(0.f);
        g_C[i]   = 0.f;
    }
    if constexpr (WITH_BIAS) {
        if (i < 2048) {
            int h = i >> 2, g = i & 3;
            g_b1p[i] = b1[g*H1 + h];
        } else if (i < 2048 + 512) {
            int c = i - 2048, h = c >> 2, g = c & 3;
            g_b2p[c] = b2[g*H2 + h];
        } else if (i < 2048 + 512 + 256) {
            int c = i - 2560, h = c >> 2, g = c & 3;
            g_b3p[c] = b3[g*H3 + h];
        }
    }
}

// ---------------- fused HMMA LSTM step (fp16 hi/lo, mixed-precision acc) ----------------
// D[128x64] = [Hprev ; x_t] x W^T: hi*hi -> fp32 acc; (hi*lo + lo*hi) -> fp16 acc
// (2x-rate encoding). Then LSTM cell. 256 threads = 8 warps (2 M x 4 N), warp
// tile 64x16, K chunks of 32. smem: 2-stage kpair words, stride 20, 60 KB dynamic.
template<int H, int IN, int LAYER>
__global__ __launch_bounds__(256, 2) void lstm_step(int t)
{
    constexpr int KT  = H + IN;
    constexpr int NCH = KT / 32;
    constexpr int STG_W = 7680;           // words per stage
    constexpr int AH_O = 0, AL_O = 2560, BH_O = 5120, BL_O = 6400;

    extern __shared__ __align__(16) uint32_t dsm[];

    const int tid  = threadIdx.x;
    const int wid  = tid >> 5;
    const int lane = tid & 31;
    const int m0   = blockIdx.x * 128;
    const int n0   = blockIdx.y * 64;
    const int wm   = (wid & 1) * 64;      // 2 warps in M
    const int wn   = (wid >> 1) * 16;     // 4 warps in N
    const int g    = lane >> 2;           // 0..7
    const int tig  = lane & 3;            // 0..3

    const __half *Hph, *Hpl, *Xh, *Xl, *Wh, *Wl;
    const float* bp;
    __half *Hnh, *Hnl, *Sh = nullptr, *Sl = nullptr;
    if constexpr (LAYER == 1) { Xh = g_Xh;  Xl = g_Xl;  Wh = g_W1h; Wl = g_W1l; bp = g_b1p; Sh = g_S1h; Sl = g_S1l; }
    else if constexpr (LAYER == 2) { Xh = g_S1h; Xl = g_S1l; Wh = g_W2h; Wl = g_W2l; bp = g_b2p; Sh = g_S2h; Sl = g_S2l; }
    else { Xh = g_S2h; Xl = g_S2l; Wh = g_W3h; Wl = g_W3l; bp = g_b3p; }
    Hph = (t & 1) ? g_HBh : g_HAh;
    Hpl = (t & 1) ? g_HBl : g_HAl;
    Hnh = (t & 1) ? g_HAh : g_HBh;
    Hnl = (t & 1) ? g_HAl : g_HBl;

    float    accF[4][2][4];
    uint32_t accH[4][2][2];
    #pragma unroll
    for (int i = 0; i < 4; i++)
        #pragma unroll
        for (int j = 0; j < 2; j++) {
            #pragma unroll
            for (int k = 0; k < 4; k++) accF[i][j][k] = 0.f;
            accH[i][j][0] = 0u; accH[i][j][1] = 0u;
        }

    // fill coordinates
    const int ar0 = tid >> 2,          aq0 = tid & 3;          // A pass 0
    const int ar1 = (tid + 256) >> 2,  aq1 = (tid + 256) & 3;  // A pass 1
    const int br_ = tid >> 2,          bq_ = tid & 3;          // B (only tid<256 rows 0..63)

    auto fill = [&](int ch, int stg) {
        const int k0 = ch * 32;
        const bool st = (k0 < H);
        uint32_t* sb = dsm + stg * STG_W;
        // A tiles: 128 rows x 4 quarters, both limbs (2 passes x 2 limbs)
        #pragma unroll
        for (int p = 0; p < 2; p++) {
            int r = p ? ar1 : ar0;
            int q = p ? aq1 : aq0;
            const __half *ah, *al;
            if (st) { ah = Hph + (size_t)(m0 + r)*H + k0;
                      al = Hpl + (size_t)(m0 + r)*H + k0; }
            else    { ah = Xh + ((size_t)(m0 + r)*TT + t)*IN + (k0 - H);
                      al = Xl + ((size_t)(m0 + r)*TT + t)*IN + (k0 - H); }
            CP_ASYNC16(smem_u32(sb + AH_O + r*20 + q*4), ah + q*8);
            CP_ASYNC16(smem_u32(sb + AL_O + r*20 + q*4), al + q*8);
        }
        // B tiles: 64 rows x 4 quarters, both limbs
        {
            const __half* wh = Wh + (size_t)(n0 + br_)*KT + k0;
            const __half* wl = Wl + (size_t)(n0 + br_)*KT + k0;
            CP_ASYNC16(smem_u32(sb + BH_O + br_*20 + bq_*4), wh + bq_*8);
            CP_ASYNC16(smem_u32(sb + BL_O + br_*20 + bq_*4), wl + bq_*8);
        }
        CP_COMMIT();
    };

    fill(0, 0);

    for (int ch = 0; ch < NCH; ch++) {
        const int stg = ch & 1;
        CP_WAIT0();
        __syncthreads();
        if (ch + 1 < NCH) fill(ch + 1, stg ^ 1);

        const uint32_t* sAh = dsm + stg*STG_W + AH_O;
        const uint32_t* sAl = dsm + stg*STG_W + AL_O;
        const uint32_t* sBh = dsm + stg*STG_W + BH_O;
        const uint32_t* sBl = dsm + stg*STG_W + BL_O;

        #pragma unroll
        for (int s = 0; s < 2; s++) {
            const int kb = s * 8;
            uint32_t bq[2][2], bl[2][2];
            #pragma unroll
            for (int j = 0; j < 2; j++) {
                int col = wn + j*8 + g;
                bq[j][0] = sBh[col*20 + kb + tig];
                bq[j][1] = sBh[col*20 + kb + 4 + tig];
                bl[j][0] = sBl[col*20 + kb + tig];
                bl[j][1] = sBl[col*20 + kb + 4 + tig];
            }
            #pragma unroll
            for (int i = 0; i < 4; i++) {
                int row = wm + i*16 + g;
                uint32_t aq[4], al[4];
                aq[0] = sAh[row*20       + kb + tig];
                aq[1] = sAh[(row + 8)*20 + kb + tig];
                aq[2] = sAh[row*20       + kb + 4 + tig];
                aq[3] = sAh[(row + 8)*20 + kb + 4 + tig];
                al[0] = sAl[row*20       + kb + tig];
                al[1] = sAl[(row + 8)*20 + kb + tig];
                al[2] = sAl[row*20       + kb + 4 + tig];
                al[3] = sAl[(row + 8)*20 + kb + 4 + tig];
                #pragma unroll
                for (int j = 0; j < 2; j++) {
                    MMA_F16_ACC32(accF[i][j], aq, bq[j]);   // hi*hi -> fp32
                    MMA_F16_ACC16(accH[i][j], aq, bl[j]);   // hi*lo -> fp16
                    MMA_F16_ACC16(accH[i][j], al, bq[j]);   // lo*hi -> fp16
                }
            }
        }
        __syncthreads();
    }

    // ---- epilogue: combine fp32 + fp16 corrections, shuffle, LSTM cell ----
    #pragma unroll
    for (int i = 0; i < 4; i++) {
        #pragma unroll
        for (int j = 0; j < 2; j++) {
            __half2 h20 = *reinterpret_cast<__half2*>(&accH[i][j][0]);
            __half2 h21 = *reinterpret_cast<__half2*>(&accH[i][j][1]);
            float c0 = accF[i][j][0] + __low2float(h20);
            float c1 = accF[i][j][1] + __high2float(h20);
            float c2 = accF[i][j][2] + __low2float(h21);
            float c3 = accF[i][j][3] + __high2float(h21);
            float s0 = __shfl_xor_sync(0xffffffffu, c0, 1);
            float s1 = __shfl_xor_sync(0xffffffffu, c1, 1);
            float s2 = __shfl_xor_sync(0xffffffffu, c2, 1);
            float s3 = __shfl_xor_sync(0xffffffffu, c3, 1);
            int row, nb;
            float g0, g1, g2, g3;
            if (!(lane & 1)) { row = wm + i*16 + g;     nb = wn + j*8 + tig*2;     g0 = c0; g1 = c1; g2 = s0; g3 = s1; }
            else             { row = wm + i*16 + g + 8; nb = wn + j*8 + tig*2 - 2; g0 = s2; g1 = s3; g2 = c2; g3 = c3; }

            const size_t m = (size_t)(m0 + row);
            const int n  = n0 + nb;            // gate-i column (n % 4 == 0)
            const int jh = n >> 2;             // h column
            float gi = g0 + bp[n + 0];
            float gf = g1 + bp[n + 1];
            float gg = g2 + bp[n + 2];
            float go = g3 + bp[n + 3];
            float iv = sigm(gi);
            float fv = sigm(gf);
            float gv = tanha(gg);
            float ov = sigm(go);
            float c  = fv * g_C[m*H + jh] + iv * gv;
            g_C[m*H + jh] = c;
            float h  = ov * tanha(c);
            __half hh, hl;
            h2split(h, hh, hl);
            Hnh[m*H + jh] = hh;
            Hnl[m*H + jh] = hl;
            float rh = fmaxf(h, 0.f);
            if constexpr (LAYER == 3) {
                g_H3seq[(m*TT + t)*H3 + jh] = rh;
            } else {
                __half rhh, rhl;
                h2split(rh, rhh, rhl);
                Sh[(m*TT + t)*H + jh] = rhh;
                Sl[(m*TT + t)*H + jh] = rhl;
            }
        }
    }
}

// ---------------- FC weight packs ----------------
__global__ void pack_wf1(const float* __restrict__ Wf1)
{
    int idx = blockIdx.x*blockDim.x + threadIdx.x;
    if (idx >= 1920*960) return;
    int k = idx / 960, n = idx % 960;
    g_Wf1p[idx] = Wf1[(size_t)n*1920 + k];
}
__global__ void pack_wf2(const float* __restrict__ Wf2)
{
    int idx = blockIdx.x*blockDim.x + threadIdx.x;
    if (idx >= 960*480) return;
    int k = idx / 480, n = idx % 480;
    g_Wf2p[idx] = Wf2[(size_t)n*960 + k];
}

// ---------------- guarded SGEMM + bias + relu for FC layers (proven) ----------------
template<int ID>
__global__ __launch_bounds__(256) void fc_gemm(const float* __restrict__ bias,
                                               int M, int N, int K)
{
    const float* __restrict__ A;
    const float* __restrict__ Bw;
    float*       __restrict__ Co;
    if constexpr (ID == 1) { A = g_D;  Bw = g_Wf1p; Co = g_F1; }
    else                   { A = g_F1; Bw = g_Wf2p; Co = g_F2; }

    __shared__ float As[16][132];
    __shared__ float Bs[16][128];

    const int m0  = blockIdx.x * 128;
    const int n0  = blockIdx.y * 128;
    const int tid = threadIdx.x;
    const int tx  = tid & 15;
    const int ty  = tid >> 4;

    float acc[8][8];
    #pragma unroll
    for (int i = 0; i < 8; i++)
        #pragma unroll
        for (int j = 0; j < 8; j++) acc[i][j] = 0.f;

    const int kl = tid & 15;
    const int ml = tid >> 4;
    const int bn = tid & 127;
    const int bk = (tid >> 7) * 8;

    for (int k0 = 0; k0 < K; k0 += 16) {
        const int kA = k0 + kl;
        #pragma unroll
        for (int i = 0; i < 8; i++) {
            int m = m0 + ml + 16*i;
            As[kl][ml + 16*i] = (kA < K) ? A[(size_t)m*K + kA] : 0.f;
        }
        const int n = n0 + bn;
        #pragma unroll
        for (int i = 0; i < 8; i++) {
            int k = k0 + bk + i;
            Bs[bk + i][bn] = (k < K && n < N) ? Bw[(size_t)k*N + n] : 0.f;
        }
        __syncthreads();
        #pragma unroll
        for (int kk = 0; kk < 16; kk++) {
            float a[8], b[8];
            #pragma unroll
            for (int i = 0; i < 8; i++) a[i] = As[kk][ty*8 + i];
            #pragma unroll
            for (int j = 0; j < 8; j++) b[j] = Bs[kk][tx*8 + j];
            #pragma unroll
            for (int i = 0; i < 8; i++)
                #pragma unroll
                for (int j = 0; j < 8; j++) acc[i][j] += a[i]*b[j];
        }
        __syncthreads();
    }

    #pragma unroll
    for (int i = 0; i < 8; i++) {
        const int m = m0 + ty*8 + i;
        #pragma unroll
        for (int j = 0; j < 8; j++) {
            const int n = n0 + tx*8 + j;
            if (n < N)
                Co[(size_t)m*N + n] = fmaxf(acc[i][j] + bias[n], 0.f);
        }
    }
}

// ---------------- |h1 - h2| ----------------
__global__ void diff_kernel()
{
    int idx = blockIdx.x*blockDim.x + threadIdx.x;
    if (idx >= BATCH*1920) return;
    int b = idx / 1920;
    int r = idx % 1920;
    int t = r / 64, h = r % 64;
    float a = g_H3seq[((size_t)b*TT + t)*64 + h];
    float c = g_H3seq[((size_t)(b + BATCH)*TT + t)*64 + h];
    g_D[idx] = fabsf(a - c);
}

// ---------------- fused FC3 + FC4 head ----------------
__global__ __launch_bounds__(256) void head_kernel(const float* __restrict__ Wf3,
                                                   const float* __restrict__ bf3,
                                                   const float* __restrict__ Wf4,
                                                   const float* __restrict__ bf4,
                                                   float* __restrict__ out)
{
    __shared__ float w3[16*480];
    __shared__ float w4[16];
    __shared__ float b3s[16];
    for (int i = threadIdx.x; i < 16*480; i += blockDim.x) w3[i] = Wf3[i];
    if (threadIdx.x < 16) { w4[threadIdx.x] = Wf4[threadIdx.x]; b3s[threadIdx.x] = bf3[threadIdx.x]; }
    __syncthreads();

    int b = blockIdx.x*blockDim.x + threadIdx.x;
    if (b >= BATCH) return;

    float acc[16];
    #pragma unroll
    for (int j = 0; j < 16; j++) acc[j] = b3s[j];

    const float* __restrict__ row = g_F2 + (size_t)b*480;
    for (int k = 0; k < 480; k++) {
        float v = row[k];
        #pragma unroll
        for (int j = 0; j < 16; j++) acc[j] += v * w3[j*480 + k];
    }
    float o = bf4[0];
    #pragma unroll
    for (int j = 0; j < 16; j++) o += fmaxf(acc[j], 0.f) * w4[j];
    out[b] = o;
}

// ---------------- launch ----------------
static const int LSTM_DSMEM = 61440;  // 2 stages x 7680 words x 4 B

extern "C" void kernel_launch(void* const* d_in, const int* in_sizes, int n_in,
                              void* d_out, int out_size)
{
    const float* x1   = (const float*)d_in[0];
    const float* x2   = (const float*)d_in[1];
    const float* Wih1 = (const float*)d_in[2];
    const float* Whh1 = (const float*)d_in[3];
    const float* b1   = (const float*)d_in[4];
    const float* Wih2 = (const float*)d_in[5];
    const float* Whh2 = (const float*)d_in[6];
    const float* b2   = (const float*)d_in[7];
    const float* Wih3 = (const float*)d_in[8];
    const float* Whh3 = (const float*)d_in[9];
    const float* b3   = (const float*)d_in[10];
    const float* Wf1  = (const float*)d_in[11];
    const float* bf1  = (const float*)d_in[12];
    const float* Wf2  = (const float*)d_in[13];
    const float* bf2  = (const float*)d_in[14];
    const float* Wf3  = (const float*)d_in[15];
    const float* bf3  = (const float*)d_in[16];
    const float* Wf4  = (const float*)d_in[17];
    const float* bf4  = (const float*)d_in[18];
    float* out = (float*)d_out;

    cudaFuncSetAttribute(lstm_step<H1, 64, 1>, cudaFuncAttributeMaxDynamicSharedMemorySize, LSTM_DSMEM);
    cudaFuncSetAttribute(lstm_step<H2, H1, 2>, cudaFuncAttributeMaxDynamicSharedMemorySize, LSTM_DSMEM);
    cudaFuncSetAttribute(lstm_step<H3, H2, 3>, cudaFuncAttributeMaxDynamicSharedMemorySize, LSTM_DSMEM);

    // launches 1-5 (keeps lstm_step<H1,t=0> at launch #6 for ncu -s 5 -c 1)
    pack_x_hilo<<<(BB*TT*64 + 255)/256, 256>>>(x1, x2);
    pack_wb<1><<<(2048*576 + 255)/256, 256>>>(Wih1, Whh1);
    pack_wb<2><<<(512*640  + 255)/256, 256>>>(Wih2, Whh2);
    pack_wb<3><<<(256*192  + 255)/256, 256>>>(Wih3, Whh3);
    zero_state_bias<true><<<(BB*H1 + 255)/256, 256>>>(b1, b2, b3);

    // layer 1: 58 -> 512   (KT = 576)
    for (int t = 0; t < TT; t++)
        lstm_step<H1, 64, 1><<<dim3(BB/128, (4*H1)/64), 256, LSTM_DSMEM>>>(t);

    // layer 2: 512 -> 128  (KT = 640)
    zero_state_bias<false><<<(BB*H1 + 255)/256, 256>>>(b1, b2, b3);
    for (int t = 0; t < TT; t++)
        lstm_step<H2, H1, 2><<<dim3(BB/128, (4*H2)/64), 256, LSTM_DSMEM>>>(t);

    // layer 3: 128 -> 64   (KT = 192)
    zero_state_bias<false><<<(BB*H1 + 255)/256, 256>>>(b1, b2, b3);
    for (int t = 0; t < TT; t++)
        lstm_step<H3, H2, 3><<<dim3(BB/128, (4*H3)/64), 256, LSTM_DSMEM>>>(t);

    pack_wf1<<<(1920*960 + 255)/256, 256>>>(Wf1);
    pack_wf2<<<(960*480  + 255)/256, 256>>>(Wf2);

    diff_kernel<<<(BATCH*1920 + 255)/256, 256>>>();

    fc_gemm<1><<<dim3(BATCH/128, (960 + 127)/128), 256>>>(bf1, BATCH, 960, 1920);
    fc_gemm<2><<<dim3(BATCH/128, (480 + 127)/128), 256>>>(bf2, BATCH, 480, 960);
    head_kernel<<<(BATCH + 255)/256, 256>>>(Wf3, bf3, Wf4, bf4, out);
}